// round 1
// baseline (speedup 1.0000x reference)
#include <cuda_runtime.h>
#include <cuda_bf16.h>

// Problem constants (fixed by setup_inputs):
//   rgb: (1, 3, 2048, 2048) float32
//   num_bins = 4, kernel_size = 3, pixel_size = 32
// Output: (1, 3, 2048, 2048) float32
//
// Semantics: for each 32x32 tile (ty, tx) of the 64x64 tile grid, look at the
// 3x3 pixel window centered at (ty*32, tx*32) (zero-padding = skip OOB).
// Each pixel gets bin = floor(mean(r,g,b)/256*4). Find the bin with the max
// pixel count (first index wins ties, matching jnp.argmax), and output
// (sum of rgb over that bin's pixels) / count, replicated over the 32x32 tile.

#define IMG_W 2048
#define IMG_H 2048
#define IMG_HW (IMG_W * IMG_H)
#define PIX 32
#define NBINS 4
#define TILES 64   // 2048 / 32

__global__ void __launch_bounds__(256, 8)
pixel_effect_kernel(const float* __restrict__ rgb, float* __restrict__ out) {
    __shared__ float s_col[3];

    const int tx = blockIdx.x;
    const int ty = blockIdx.y;
    const int cx = tx * PIX;
    const int cy = ty * PIX;

    if (threadIdx.x == 0) {
        float cnt[NBINS];
        float sr[NBINS], sg[NBINS], sb[NBINS];
#pragma unroll
        for (int i = 0; i < NBINS; i++) {
            cnt[i] = 0.0f; sr[i] = 0.0f; sg[i] = 0.0f; sb[i] = 0.0f;
        }

#pragma unroll
        for (int dy = -1; dy <= 1; dy++) {
            const int y = cy + dy;
            if ((unsigned)y >= (unsigned)IMG_H) continue;
#pragma unroll
            for (int dx = -1; dx <= 1; dx++) {
                const int x = cx + dx;
                if ((unsigned)x >= (unsigned)IMG_W) continue;
                const int p = y * IMG_W + x;
                const float r = rgb[p];
                const float g = rgb[IMG_HW + p];
                const float b = rgb[2 * IMG_HW + p];
                // match reference: mean = (r+g+b)/3; idx = int(mean/256*4)
                const float m = (r + g + b) / 3.0f;
                int bin = (int)(m / 256.0f * (float)NBINS);
                bin = min(max(bin, 0), NBINS - 1);  // safety clamp (unreachable)
                cnt[bin] += 1.0f;
                sr[bin] += r; sg[bin] += g; sb[bin] += b;
            }
        }

        // argmax over bins, first-max wins (strict >), matching jnp.argmax
        int best = 0;
#pragma unroll
        for (int i = 1; i < NBINS; i++) {
            if (cnt[i] > cnt[best]) best = i;
        }
        const float c = cnt[best];  // >= 1 always (window has >= 4 valid pixels)
        s_col[0] = sr[best] / c;
        s_col[1] = sg[best] / c;
        s_col[2] = sb[best] / c;
    }
    __syncthreads();

    const float c0 = s_col[0];
    const float c1 = s_col[1];
    const float c2 = s_col[2];

    // 256 threads write the 32x32 tile for all 3 channels as float4 stores.
    // tid -> (row, vec4-within-row): 32 rows * 8 float4 per row = 256.
    const int tid = threadIdx.x;
    const int row = tid >> 3;
    const int v   = tid & 7;
    const int y = cy + row;
    const int x = cx + v * 4;
    const long base = (long)y * IMG_W + x;  // multiple of 4 -> 16B aligned

    float4* o4 = reinterpret_cast<float4*>(out);
    o4[(0L * IMG_HW + base) >> 2] = make_float4(c0, c0, c0, c0);
    o4[(1L * IMG_HW + base) >> 2] = make_float4(c1, c1, c1, c1);
    o4[(2L * IMG_HW + base) >> 2] = make_float4(c2, c2, c2, c2);
}

extern "C" void kernel_launch(void* const* d_in, const int* in_sizes, int n_in,
                              void* d_out, int out_size) {
    const float* rgb = (const float*)d_in[0];
    float* out = (float*)d_out;
    dim3 grid(TILES, TILES);
    dim3 block(256);
    pixel_effect_kernel<<<grid, block>>>(rgb, out);
}

// round 2
// speedup vs baseline: 1.2544x; 1.2544x over previous
#include <cuda_runtime.h>
#include <cuda_bf16.h>

// rgb: (1, 3, 2048, 2048) f32; num_bins=4, kernel=3, pixel_size=32.
// Out: (1, 3, 2048, 2048) f32.
//
// Per 32x32 tile: bin the <=9 pixels of the 3x3 window at the tile origin by
// floor(mean(r,g,b)/256*4); dominant bin (first-max) -> color = sum/count,
// replicated over the tile.
//
// Two-phase: A computes 64x64x3 tile colors into device scratch (latency
// phase, tiny); B is a pure bandwidth fill (store phase, no barriers).

#define IMG_W 2048
#define IMG_H 2048
#define IMG_HW (IMG_W * IMG_H)
#define PIX 32
#define NBINS 4
#define TILES 64         // 2048/32
#define NTILES (TILES * TILES)

__device__ float g_tile_col[3 * NTILES];   // [channel][tile]

// ---------------- Phase A: one thread per tile ----------------
__global__ void __launch_bounds__(32)
compute_colors_kernel(const float* __restrict__ rgb) {
    const int tile = blockIdx.x * 32 + threadIdx.x;
    if (tile >= NTILES) return;
    const int tx = tile & (TILES - 1);
    const int ty = tile >> 6;
    const int cx = tx * PIX;
    const int cy = ty * PIX;

    float cnt[NBINS], sr[NBINS], sg[NBINS], sb[NBINS];
#pragma unroll
    for (int i = 0; i < NBINS; i++) { cnt[i] = 0.f; sr[i] = 0.f; sg[i] = 0.f; sb[i] = 0.f; }

#pragma unroll
    for (int dy = -1; dy <= 1; dy++) {
        const int y = cy + dy;
        if ((unsigned)y >= (unsigned)IMG_H) continue;
#pragma unroll
        for (int dx = -1; dx <= 1; dx++) {
            const int x = cx + dx;
            if ((unsigned)x >= (unsigned)IMG_W) continue;
            const int p = y * IMG_W + x;
            const float r = rgb[p];
            const float g = rgb[IMG_HW + p];
            const float b = rgb[2 * IMG_HW + p];
            const float m = (r + g + b) / 3.0f;           // match jnp.mean
            int bin = (int)(m / 256.0f * (float)NBINS);   // trunc, matches astype(int32)
            bin = min(max(bin, 0), NBINS - 1);
            cnt[bin] += 1.0f;
            sr[bin] += r; sg[bin] += g; sb[bin] += b;
        }
    }

    int best = 0;
#pragma unroll
    for (int i = 1; i < NBINS; i++)
        if (cnt[i] > cnt[best]) best = i;   // first-max, matches jnp.argmax
    const float inv = 1.0f;                 // keep true division for bit-match
    g_tile_col[tile]              = sr[best] / cnt[best];
    g_tile_col[NTILES + tile]     = sg[best] / cnt[best];
    g_tile_col[2 * NTILES + tile] = sb[best] / cnt[best];
    (void)inv;
}

// ---------------- Phase B: block per tile, pure fill ----------------
__global__ void __launch_bounds__(256, 8)
fill_kernel(float* __restrict__ out) {
    const int tile = blockIdx.x;
    const int tx = tile & (TILES - 1);
    const int ty = tile >> 6;

    // Same address across the warp -> single broadcast LDG (L2-hot).
    const float c0 = g_tile_col[tile];
    const float c1 = g_tile_col[NTILES + tile];
    const float c2 = g_tile_col[2 * NTILES + tile];

    const int tid = threadIdx.x;
    const int row = tid >> 3;     // 0..31
    const int v   = tid & 7;      // 0..7 float4s within the 32-wide tile row
    const int y = ty * PIX + row;
    const int x = tx * PIX + v * 4;
    const long base = (long)y * IMG_W + x;   // 16B aligned

    float4* o4 = reinterpret_cast<float4*>(out);
    o4[(0L * IMG_HW + base) >> 2] = make_float4(c0, c0, c0, c0);
    o4[(1L * IMG_HW + base) >> 2] = make_float4(c1, c1, c1, c1);
    o4[(2L * IMG_HW + base) >> 2] = make_float4(c2, c2, c2, c2);
}

extern "C" void kernel_launch(void* const* d_in, const int* in_sizes, int n_in,
                              void* d_out, int out_size) {
    const float* rgb = (const float*)d_in[0];
    float* out = (float*)d_out;

    compute_colors_kernel<<<NTILES / 32, 32>>>(rgb);
    fill_kernel<<<NTILES, 256>>>(out);
}